// round 14
// baseline (speedup 1.0000x reference)
#include <cuda_runtime.h>

#define NPTS 65536
#define NSMP 16
#define NSAMPLES (NPTS * NSMP)
#define CNT ((float)NSAMPLES)
#define EPS 1e-5f
#define GEMM_BLOCKS 1024

// ---------------- static device scratch ------------------------------------
__device__ float g_xq[NPTS * 64];
__device__ float g_xk[NPTS * 64];
__device__ float g_xv[NPTS * 64];
__device__ float g_w8[NSAMPLES * 8];
__device__ float4 g_jr[NSAMPLES];  // (a0, a1, a2, idx-as-float) per sample
__device__ float g_pP[6][1024];    // per-block partial sums of positional stats
__device__ float g_sPf[6];         // finalized positional sums
__device__ float g_sW1[128];       // sum[64], sumsq[64]
__device__ float g_sW2[16];        // sum[8],  sumsq[8]

// ---------------- f32x2 helpers ---------------------------------------------
typedef unsigned long long ull;
__device__ __forceinline__ ull fma2(ull a, ull b, ull c) {
    ull d;
    asm("fma.rn.f32x2 %0, %1, %2, %3;" : "=l"(d) : "l"(a), "l"(b), "l"(c));
    return d;
}
__device__ __forceinline__ ull add2(ull a, ull b) {
    ull d;
    asm("add.rn.f32x2 %0, %1, %2;" : "=l"(d) : "l"(a), "l"(b));
    return d;
}
__device__ __forceinline__ ull dup2(float v) {
    ull d;
    asm("mov.b64 %0, {%1, %1};" : "=l"(d) : "r"(__float_as_uint(v)));
    return d;
}
__device__ __forceinline__ ull pack2(float lo, float hi) {
    ull d;
    asm("mov.b64 %0, {%1, %2};" : "=l"(d) : "r"(__float_as_uint(lo)), "r"(__float_as_uint(hi)));
    return d;
}
__device__ __forceinline__ void unpack2(ull v, float& lo, float& hi) {
    unsigned int a, b;
    asm("mov.b64 {%0, %1}, %2;" : "=r"(a), "=r"(b) : "l"(v));
    lo = __uint_as_float(a); hi = __uint_as_float(b);
}

// ---------------- K1: fused QKV GEMM + positional stats pass -----------------
// grid 2048, block 256. blocks [0,1024): gemm (loop q,k,v); [1024,2048): statsP.
__global__ __launch_bounds__(256) void k_gemm_statsP(
    const float* __restrict__ x, const float* __restrict__ p,
    const int* __restrict__ idx,
    const float* __restrict__ Wq, const float* __restrict__ bq,
    const float* __restrict__ Wk, const float* __restrict__ bk,
    const float* __restrict__ Wv, const float* __restrict__ bv,
    const float* __restrict__ Wp1, const float* __restrict__ bp1) {
    __shared__ __align__(16) float xs[64 * 68];
    __shared__ __align__(16) float ws[64 * 68];
    __shared__ float red[8][6];
    const int bid = blockIdx.x;
    const int t = threadIdx.x;

    if (bid < GEMM_BLOCKS) {
        if (bid == 0) {
            if (t < 128) g_sW1[t] = 0.f;
            if (t < 16)  g_sW2[t] = 0.f;
        }
        const int pbase = bid * 64;
        for (int e = t; e < 4096; e += 256) {
            int r = e >> 6, j = e & 63;
            xs[j * 68 + r] = x[(pbase + r) * 64 + j];
        }
        const float* Ws[3] = {Wq, Wk, Wv};
        const float* Bs[3] = {bq, bk, bv};
        float* Os[3] = {g_xq, g_xk, g_xv};
        const int tx = t & 15;
        const int ty = t >> 4;
#pragma unroll
        for (int m = 0; m < 3; m++) {
            __syncthreads();
            const float* W = Ws[m];
            for (int e = t; e < 4096; e += 256) {
                int r = e >> 6, j = e & 63;
                ws[j * 68 + r] = W[r * 64 + j];
            }
            __syncthreads();

            ull acc[4][2];
#pragma unroll
            for (int i = 0; i < 4; i++) { acc[i][0] = 0ULL; acc[i][1] = 0ULL; }
            const float4* xp = (const float4*)(xs + ty * 4);
#pragma unroll 8
            for (int j = 0; j < 64; j++) {
                float4 xv4 = xp[j * 17];
                ulonglong2 w2 = *(const ulonglong2*)(ws + j * 68 + tx * 4);
                ull X;
                X = dup2(xv4.x); acc[0][0] = fma2(X, w2.x, acc[0][0]); acc[0][1] = fma2(X, w2.y, acc[0][1]);
                X = dup2(xv4.y); acc[1][0] = fma2(X, w2.x, acc[1][0]); acc[1][1] = fma2(X, w2.y, acc[1][1]);
                X = dup2(xv4.z); acc[2][0] = fma2(X, w2.x, acc[2][0]); acc[2][1] = fma2(X, w2.y, acc[2][1]);
                X = dup2(xv4.w); acc[3][0] = fma2(X, w2.x, acc[3][0]); acc[3][1] = fma2(X, w2.y, acc[3][1]);
            }
            float4 bo = *(const float4*)(Bs[m] + tx * 4);
            float* out = Os[m];
#pragma unroll
            for (int pp = 0; pp < 4; pp++) {
                float c0, c1, c2, c3;
                unpack2(acc[pp][0], c0, c1);
                unpack2(acc[pp][1], c2, c3);
                *(float4*)(out + (pbase + ty * 4 + pp) * 64 + tx * 4) =
                    make_float4(c0 + bo.x, c1 + bo.y, c2 + bo.z, c3 + bo.w);
            }
        }
    } else {
        const int sbid = bid - GEMM_BLOCKS;
        float w00 = Wp1[0], w01 = Wp1[1], w02 = Wp1[2];
        float w10 = Wp1[3], w11 = Wp1[4], w12 = Wp1[5];
        float w20 = Wp1[6], w21 = Wp1[7], w22 = Wp1[8];
        float b0 = bp1[0], b1 = bp1[1], b2 = bp1[2];

        float s0 = 0, s1 = 0, s2 = 0, q0 = 0, q1 = 0, q2 = 0;
        int bbase = sbid * 1024;
#pragma unroll
        for (int i = 0; i < 4; i++) {
            int sid = bbase + i * 256 + t;
            int n = sid >> 4;
            int j = idx[sid];
            float dx = p[j * 3 + 0] - p[n * 3 + 0];
            float dy = p[j * 3 + 1] - p[n * 3 + 1];
            float dz = p[j * 3 + 2] - p[n * 3 + 2];
            float a0 = w00 * dx + w01 * dy + w02 * dz + b0;
            float a1 = w10 * dx + w11 * dy + w12 * dz + b1;
            float a2 = w20 * dx + w21 * dy + w22 * dz + b2;
            g_jr[sid] = make_float4(a0, a1, a2, __int_as_float(j));
            s0 += a0; s1 += a1; s2 += a2;
            q0 += a0 * a0; q1 += a1 * a1; q2 += a2 * a2;
        }
#pragma unroll
        for (int o = 16; o; o >>= 1) {
            s0 += __shfl_xor_sync(0xffffffffu, s0, o);
            s1 += __shfl_xor_sync(0xffffffffu, s1, o);
            s2 += __shfl_xor_sync(0xffffffffu, s2, o);
            q0 += __shfl_xor_sync(0xffffffffu, q0, o);
            q1 += __shfl_xor_sync(0xffffffffu, q1, o);
            q2 += __shfl_xor_sync(0xffffffffu, q2, o);
        }
        int w = t >> 5, lane = t & 31;
        if (lane == 0) {
            red[w][0] = s0; red[w][1] = s1; red[w][2] = s2;
            red[w][3] = q0; red[w][4] = q1; red[w][5] = q2;
        }
        __syncthreads();
        if (t < 6) {
            float acc = 0.f;
#pragma unroll
            for (int i = 0; i < 8; i++) acc += red[i][t];
            g_pP[t][sbid] = acc;
        }
    }
}

// ---------------- K3: stats of w = xk[idx] - xq + p_r2 -----------------------
__global__ __launch_bounds__(256) void k_statsW1(
    const float* __restrict__ Wp2, const float* __restrict__ bp2,
    const float* __restrict__ gp, const float* __restrict__ betap) {
    __shared__ __align__(16) float4 sh_jr[8][128];
    __shared__ float sred[128];
    __shared__ float sP6[6];
    int t = threadIdx.x, w = t >> 5, l = t & 31;

    if (t < 192) {
        int ch = t >> 5, ln = t & 31;
        float s = 0.f;
#pragma unroll
        for (int i = 0; i < 32; i++) s += g_pP[ch][ln + 32 * i];
#pragma unroll
        for (int o = 16; o; o >>= 1) s += __shfl_xor_sync(0xffffffffu, s, o);
        if (ln == 0) sP6[ch] = s;
    }
    if (t < 128) sred[t] = 0.f;
    __syncthreads();
    if (blockIdx.x == 0 && t < 6) g_sPf[t] = sP6[t];

    float aP[3], bP[3];
#pragma unroll
    for (int c = 0; c < 3; c++) {
        float m = sP6[c] / CNT;
        float v = sP6[3 + c] / CNT - m * m;
        aP[c] = gp[c] * rsqrtf(v + EPS);
        bP[c] = betap[c] - m * aP[c];
    }

    const int c0 = 2 * l;
    ull WA0 = pack2(Wp2[c0 * 3],     Wp2[(c0 + 1) * 3]);
    ull WA1 = pack2(Wp2[c0 * 3 + 1], Wp2[(c0 + 1) * 3 + 1]);
    ull WA2 = pack2(Wp2[c0 * 3 + 2], Wp2[(c0 + 1) * 3 + 2]);
    float bq0 = bp2[c0], bq1 = bp2[c0 + 1];

    int pwarp = (blockIdx.x * 8 + w) * 8;
#pragma unroll
    for (int i = 0; i < 4; i++) {
        int sl = 32 * i + l;
        int sid = pwarp * 16 + sl;
        float4 a = g_jr[sid];
        float r0 = fmaxf(aP[0] * a.x + bP[0], 0.f);
        float r1 = fmaxf(aP[1] * a.y + bP[1], 0.f);
        float r2 = fmaxf(aP[2] * a.z + bP[2], 0.f);
        sh_jr[w][sl] = make_float4(r0, r1, r2, a.w);
    }
    __syncwarp();

    ull S = 0ULL, SS = 0ULL;
#pragma unroll
    for (int pp = 0; pp < 8; pp++) {
        int n = pwarp + pp;
        float2 q2 = *(const float2*)(g_xq + n * 64 + c0);
        ull base = pack2(bq0 - q2.x, bq1 - q2.y);
#pragma unroll
        for (int k = 0; k < 16; k++) {
            float4 jr = sh_jr[w][pp * 16 + k];
            int j = __float_as_int(jr.w);
            ull pr = fma2(dup2(jr.z), WA2,
                      fma2(dup2(jr.y), WA1,
                      fma2(dup2(jr.x), WA0, base)));
            ull xk2 = *(const ull*)(g_xk + j * 64 + c0);
            ull wv = add2(xk2, pr);
            S  = add2(S, wv);
            SS = fma2(wv, wv, SS);
        }
    }
    float s0, s1, q0, q1;
    unpack2(S, s0, s1);
    unpack2(SS, q0, q1);
    atomicAdd(&sred[c0], s0);
    atomicAdd(&sred[c0 + 1], s1);
    atomicAdd(&sred[64 + c0], q0);
    atomicAdd(&sred[64 + c0 + 1], q1);
    __syncthreads();
    if (t < 128) atomicAdd(&g_sW1[t], sred[t]);
}

// ---------------- BN-P constants from finalized sums -------------------------
__device__ __forceinline__ void bnp_coef_f(const float* gp, const float* betap,
                                           float* aP, float* bP) {
#pragma unroll
    for (int c = 0; c < 3; c++) {
        float m = g_sPf[c] / CNT;
        float v = g_sPf[3 + c] / CNT - m * m;
        aP[c] = gp[c] * rsqrtf(v + EPS);
        bP[c] = betap[c] - m * aP[c];
    }
}

// ---------------- K4: w8 = relu(bn1(w)) @ Ww1^T + bw1, + stats ---------------
// grid 2048; block 128 (4 warps); warp handles 8 points in 8 tiles of 1 point.
// Phase B: lane pair (l, l+16) splits one sample's 64 channels.
__global__ __launch_bounds__(128) void k_w8(
    const float* __restrict__ Wp2, const float* __restrict__ bp2,
    const float* __restrict__ gp, const float* __restrict__ betap,
    const float* __restrict__ gw1, const float* __restrict__ betaw1,
    const float* __restrict__ Ww1, const float* __restrict__ bw1) {
    __shared__ __align__(16) float sh_h[4][16 * 68];
    __shared__ __align__(16) float4 sh_jr[4][16];
    __shared__ __align__(16) float ww1s[8][64];
    __shared__ float sred2[16];
    int t = threadIdx.x, w = t >> 5, l = t & 31;
    if (t < 16) sred2[t] = 0.f;
    for (int e = t; e < 512; e += 128) ww1s[e >> 6][e & 63] = Ww1[e];

    float aP[3], bP[3];
    bnp_coef_f(gp, betap, aP, bP);

    const int c0 = 2 * l;
    ull WA0 = pack2(Wp2[c0 * 3],     Wp2[(c0 + 1) * 3]);
    ull WA1 = pack2(Wp2[c0 * 3 + 1], Wp2[(c0 + 1) * 3 + 1]);
    ull WA2 = pack2(Wp2[c0 * 3 + 2], Wp2[(c0 + 1) * 3 + 2]);
    float bq0 = bp2[c0], bq1 = bp2[c0 + 1];

    float m0 = g_sW1[c0] / CNT,     v0 = g_sW1[64 + c0] / CNT - m0 * m0;
    float A0 = gw1[c0] * rsqrtf(v0 + EPS), B0 = betaw1[c0] - m0 * A0;
    float m1 = g_sW1[c0 + 1] / CNT, v1 = g_sW1[64 + c0 + 1] / CNT - m1 * m1;
    float A1 = gw1[c0 + 1] * rsqrtf(v1 + EPS), B1 = betaw1[c0 + 1] - m1 * A1;
    ull A1p = pack2(A0, A1), B1p = pack2(B0, B1);

    float bw[8];
#pragma unroll
    for (int r = 0; r < 8; r++) bw[r] = bw1[r];
    float sw[8], sq[8];
#pragma unroll
    for (int r = 0; r < 8; r++) { sw[r] = 0.f; sq[r] = 0.f; }

    const int smp = l & 15;   // phase-B: sample this lane works on
    const int hf  = l >> 4;   // phase-B: channel half (0: 0-31, 1: 32-63)
    int pwarp = (blockIdx.x * 4 + w) * 8;
    __syncthreads();

    for (int tt = 0; tt < 8; tt++) {
        int pA = pwarp + tt;
        if (l < 16) {   // stage 1 point x 16 neighbors
            int sid = pA * 16 + l;
            float4 a = g_jr[sid];
            float r0 = fmaxf(aP[0] * a.x + bP[0], 0.f);
            float r1 = fmaxf(aP[1] * a.y + bP[1], 0.f);
            float r2 = fmaxf(aP[2] * a.z + bP[2], 0.f);
            sh_jr[w][l] = make_float4(r0, r1, r2, a.w);
        }
        float2 qA = *(const float2*)(g_xq + pA * 64 + c0);
        ull base = pack2(bq0 - qA.x, bq1 - qA.y);
        __syncwarp();
        // phase A: h = relu(bn1(w)) into shared, sample-major rows (16 rows)
#pragma unroll
        for (int kk = 0; kk < 16; kk++) {
            float4 jr = sh_jr[w][kk];
            int j = __float_as_int(jr.w);
            ull pr = fma2(dup2(jr.z), WA2,
                      fma2(dup2(jr.y), WA1,
                      fma2(dup2(jr.x), WA0, base)));
            ull xk2 = *(const ull*)(g_xk + j * 64 + c0);
            ull u = add2(xk2, pr);
            ull hp = fma2(A1p, u, B1p);
            float h0, h1;
            unpack2(hp, h0, h1);
            h0 = fmaxf(h0, 0.f); h1 = fmaxf(h1, 0.f);
            *(ull*)(sh_h[w] + kk * 68 + c0) = pack2(h0, h1);
        }
        __syncwarp();
        // phase B: lane pair shares one sample; matvec 64 -> 8 (half each)
        ull Y[8];
#pragma unroll
        for (int r = 0; r < 8; r++) Y[r] = 0ULL;
        const ulonglong2* hv = (const ulonglong2*)(sh_h[w] + smp * 68 + hf * 32);
#pragma unroll
        for (int cc = 0; cc < 8; cc++) {
            ulonglong2 h2 = hv[cc];
#pragma unroll
            for (int r = 0; r < 8; r++) {
                ulonglong2 w2 = *(const ulonglong2*)(&ww1s[r][hf * 32 + cc * 4]);
                Y[r] = fma2(h2.x, w2.x, Y[r]);
                Y[r] = fma2(h2.y, w2.y, Y[r]);
            }
        }
        float y[8];
#pragma unroll
        for (int r = 0; r < 8; r++) {
            float a, b;
            unpack2(Y[r], a, b);
            y[r] = a + b;
            y[r] += __shfl_xor_sync(0xffffffffu, y[r], 16);
            y[r] += bw[r];
        }
        int sid = pA * 16 + smp;
        if (hf == 0) {
            *(float4*)(g_w8 + sid * 8) = make_float4(y[0], y[1], y[2], y[3]);
#pragma unroll
            for (int r = 0; r < 8; r++) { sw[r] += y[r]; sq[r] += y[r] * y[r]; }
        } else {
            *(float4*)(g_w8 + sid * 8 + 4) = make_float4(y[4], y[5], y[6], y[7]);
        }
        __syncwarp();
    }
    // reduce stats over lanes 0-15 (holders)
#pragma unroll
    for (int o = 8; o; o >>= 1) {
#pragma unroll
        for (int r = 0; r < 8; r++) {
            sw[r] += __shfl_xor_sync(0xffffffffu, sw[r], o);
            sq[r] += __shfl_xor_sync(0xffffffffu, sq[r], o);
        }
    }
    if (l == 0) {
#pragma unroll
        for (int r = 0; r < 8; r++) {
            atomicAdd(&sred2[r], sw[r]);
            atomicAdd(&sred2[8 + r], sq[r]);
        }
    }
    __syncthreads();
    if (t < 16) atomicAdd(&g_sW2[t], sred2[t]);
}

// ---------------- K5: bn2 + relu + 8x8 matvec + softmax + aggregate ----------
// grid 4096; block 256 (8 warps); warp handles 2 points.
__global__ __launch_bounds__(256) void k_final(
    const float* __restrict__ Wp2, const float* __restrict__ bp2,
    const float* __restrict__ gp, const float* __restrict__ betap,
    const float* __restrict__ gw2, const float* __restrict__ betaw2,
    const float* __restrict__ Ww2, const float* __restrict__ bw2,
    float* __restrict__ out) {
    __shared__ __align__(16) ull sh_sT[8][32][5];  // [warp][sample][mpair+pad]
    __shared__ __align__(16) float4 sh_jr[8][32];
    int t = threadIdx.x, w = t >> 5, l = t & 31;

    float aP[3], bP[3];
    bnp_coef_f(gp, betap, aP, bP);

    float A2[8], B2[8];
#pragma unroll
    for (int r = 0; r < 8; r++) {
        float m = g_sW2[r] / CNT;
        float v = g_sW2[8 + r] / CNT - m * m;
        A2[r] = gw2[r] * rsqrtf(v + EPS);
        B2[r] = betaw2[r] - m * A2[r];
    }

    const int c0 = 2 * l;
    ull WA0 = pack2(Wp2[c0 * 3],     Wp2[(c0 + 1) * 3]);
    ull WA1 = pack2(Wp2[c0 * 3 + 1], Wp2[(c0 + 1) * 3 + 1]);
    ull WA2 = pack2(Wp2[c0 * 3 + 2], Wp2[(c0 + 1) * 3 + 2]);
    ull BBp = pack2(bp2[c0], bp2[c0 + 1]);

    int pbase = (blockIdx.x * 8 + w) * 2;
    int sid = (pbase + (l >> 4)) * 16 + (l & 15);
    {
        float4 a = g_jr[sid];
        float r0 = fmaxf(aP[0] * a.x + bP[0], 0.f);
        float r1 = fmaxf(aP[1] * a.y + bP[1], 0.f);
        float r2 = fmaxf(aP[2] * a.z + bP[2], 0.f);
        sh_jr[w][l] = make_float4(r0, r1, r2, a.w);
    }

    float4 y0 = *(const float4*)(g_w8 + sid * 8);
    float4 y1 = *(const float4*)(g_w8 + sid * 8 + 4);
    float h[8] = {y0.x, y0.y, y0.z, y0.w, y1.x, y1.y, y1.z, y1.w};
#pragma unroll
    for (int r = 0; r < 8; r++) h[r] = fmaxf(A2[r] * h[r] + B2[r], 0.f);

    float z[8];
#pragma unroll
    for (int r = 0; r < 8; r++) {
        float acc = bw2[r];
#pragma unroll
        for (int i = 0; i < 8; i++) acc += h[i] * Ww2[r * 8 + i];
        z[r] = acc;
    }
    // softmax over 16 neighbors (xor <= 8 keeps 16-lane halves independent)
#pragma unroll
    for (int r = 0; r < 8; r++) {
        float mx = z[r];
#pragma unroll
        for (int o = 8; o; o >>= 1) mx = fmaxf(mx, __shfl_xor_sync(0xffffffffu, mx, o));
        float e = __expf(z[r] - mx);
        float sm = e;
#pragma unroll
        for (int o = 8; o; o >>= 1) sm += __shfl_xor_sync(0xffffffffu, sm, o);
        z[r] = e / sm;
    }
    // conflict-free padded store: lane-major rows, pair index within row
#pragma unroll
    for (int p2 = 0; p2 < 4; p2++)
        sh_sT[w][l][p2] = pack2(z[2 * p2], z[2 * p2 + 1]);
    __syncwarp();

    // aggregate: lane l owns channels (2l, 2l+1)
    const int mp = l & 3;
#pragma unroll
    for (int pp = 0; pp < 2; pp++) {
        int n = pbase + pp;
        ull ACC = 0ULL;
#pragma unroll
        for (int k = 0; k < 16; k++) {
            int kk = pp * 16 + k;
            float4 jr = sh_jr[w][kk];
            int jg = __float_as_int(jr.w);
            ull pr = fma2(dup2(jr.z), WA2,
                      fma2(dup2(jr.y), WA1,
                      fma2(dup2(jr.x), WA0, BBp)));
            ull xv2 = *(const ull*)(g_xv + jg * 64 + c0);
            ull tv = add2(xv2, pr);
            ull s2 = sh_sT[w][kk][mp];
            ACC = fma2(tv, s2, ACC);
        }
        float a0, a1;
        unpack2(ACC, a0, a1);
        *(float2*)(out + n * 64 + c0) = make_float2(a0, a1);
    }
}

// ---------------- launch ------------------------------------------------------
extern "C" void kernel_launch(void* const* d_in, const int* in_sizes, int n_in,
                              void* d_out, int out_size) {
    const float* p     = (const float*)d_in[0];
    const float* x     = (const float*)d_in[1];
    const int*   idx   = (const int*)d_in[2];
    const float* Wq    = (const float*)d_in[3];
    const float* bq    = (const float*)d_in[4];
    const float* Wk    = (const float*)d_in[5];
    const float* bk    = (const float*)d_in[6];
    const float* Wv    = (const float*)d_in[7];
    const float* bv    = (const float*)d_in[8];
    const float* Wp1   = (const float*)d_in[9];
    const float* bp1   = (const float*)d_in[10];
    const float* gp    = (const float*)d_in[11];
    const float* betap = (const float*)d_in[12];
    const float* Wp2   = (const float*)d_in[13];
    const float* bp2   = (const float*)d_in[14];
    const float* gw1   = (const float*)d_in[15];
    const float* betaw1= (const float*)d_in[16];
    const float* Ww1   = (const float*)d_in[17];
    const float* bw1   = (const float*)d_in[18];
    const float* gw2   = (const float*)d_in[19];
    const float* betaw2= (const float*)d_in[20];
    const float* Ww2   = (const float*)d_in[21];
    const float* bw2   = (const float*)d_in[22];
    float* out = (float*)d_out;

    k_gemm_statsP<<<2048, 256>>>(x, p, idx, Wq, bq, Wk, bk, Wv, bv, Wp1, bp1);
    k_statsW1<<<1024, 256>>>(Wp2, bp2, gp, betap);
    k_w8<<<2048, 128>>>(Wp2, bp2, gp, betap, gw1, betaw1, Ww1, bw1);
    k_final<<<4096, 256>>>(Wp2, bp2, gp, betap, gw2, betaw2, Ww2, bw2, out);
}

// round 15
// speedup vs baseline: 1.0842x; 1.0842x over previous
#include <cuda_runtime.h>

#define NPTS 65536
#define NSMP 16
#define NSAMPLES (NPTS * NSMP)
#define CNT ((float)NSAMPLES)
#define EPS 1e-5f
#define GEMM_BLOCKS 1024

// ---------------- static device scratch ------------------------------------
__device__ float g_xq[NPTS * 64];
__device__ float g_xk[NPTS * 64];
__device__ float g_xv[NPTS * 64];
__device__ float g_w8[NSAMPLES * 8];
__device__ float4 g_jr[NSAMPLES];  // (a0, a1, a2, idx-as-float) per sample
__device__ float g_pP[6][1024];    // per-block partial sums of positional stats
__device__ float g_sPf[6];         // finalized positional sums
__device__ float g_sW1[128];       // sum[64], sumsq[64]
__device__ float g_sW2[16];        // sum[8],  sumsq[8]

// ---------------- f32x2 helpers ---------------------------------------------
typedef unsigned long long ull;
__device__ __forceinline__ ull fma2(ull a, ull b, ull c) {
    ull d;
    asm("fma.rn.f32x2 %0, %1, %2, %3;" : "=l"(d) : "l"(a), "l"(b), "l"(c));
    return d;
}
__device__ __forceinline__ ull add2(ull a, ull b) {
    ull d;
    asm("add.rn.f32x2 %0, %1, %2;" : "=l"(d) : "l"(a), "l"(b));
    return d;
}
__device__ __forceinline__ ull dup2(float v) {
    ull d;
    asm("mov.b64 %0, {%1, %1};" : "=l"(d) : "r"(__float_as_uint(v)));
    return d;
}
__device__ __forceinline__ ull pack2(float lo, float hi) {
    ull d;
    asm("mov.b64 %0, {%1, %2};" : "=l"(d) : "r"(__float_as_uint(lo)), "r"(__float_as_uint(hi)));
    return d;
}
__device__ __forceinline__ void unpack2(ull v, float& lo, float& hi) {
    unsigned int a, b;
    asm("mov.b64 {%0, %1}, %2;" : "=r"(a), "=r"(b) : "l"(v));
    lo = __uint_as_float(a); hi = __uint_as_float(b);
}

// ---------------- K1: fused QKV GEMM + positional stats pass -----------------
// grid 2048, block 256. blocks [0,1024): gemm (loop q,k,v); [1024,2048): statsP.
__global__ __launch_bounds__(256) void k_gemm_statsP(
    const float* __restrict__ x, const float* __restrict__ p,
    const int* __restrict__ idx,
    const float* __restrict__ Wq, const float* __restrict__ bq,
    const float* __restrict__ Wk, const float* __restrict__ bk,
    const float* __restrict__ Wv, const float* __restrict__ bv,
    const float* __restrict__ Wp1, const float* __restrict__ bp1) {
    __shared__ __align__(16) float xs[64 * 68];
    __shared__ __align__(16) float ws[64 * 68];
    __shared__ float red[8][6];
    const int bid = blockIdx.x;
    const int t = threadIdx.x;

    if (bid < GEMM_BLOCKS) {
        if (bid == 0) {
            if (t < 128) g_sW1[t] = 0.f;
            if (t < 16)  g_sW2[t] = 0.f;
        }
        const int pbase = bid * 64;
        for (int e = t; e < 4096; e += 256) {
            int r = e >> 6, j = e & 63;
            xs[j * 68 + r] = x[(pbase + r) * 64 + j];
        }
        const float* Ws[3] = {Wq, Wk, Wv};
        const float* Bs[3] = {bq, bk, bv};
        float* Os[3] = {g_xq, g_xk, g_xv};
        const int tx = t & 15;
        const int ty = t >> 4;
#pragma unroll
        for (int m = 0; m < 3; m++) {
            __syncthreads();
            const float* W = Ws[m];
            for (int e = t; e < 4096; e += 256) {
                int r = e >> 6, j = e & 63;
                ws[j * 68 + r] = W[r * 64 + j];
            }
            __syncthreads();

            ull acc[4][2];
#pragma unroll
            for (int i = 0; i < 4; i++) { acc[i][0] = 0ULL; acc[i][1] = 0ULL; }
            const float4* xp = (const float4*)(xs + ty * 4);
#pragma unroll 8
            for (int j = 0; j < 64; j++) {
                float4 xv4 = xp[j * 17];
                ulonglong2 w2 = *(const ulonglong2*)(ws + j * 68 + tx * 4);
                ull X;
                X = dup2(xv4.x); acc[0][0] = fma2(X, w2.x, acc[0][0]); acc[0][1] = fma2(X, w2.y, acc[0][1]);
                X = dup2(xv4.y); acc[1][0] = fma2(X, w2.x, acc[1][0]); acc[1][1] = fma2(X, w2.y, acc[1][1]);
                X = dup2(xv4.z); acc[2][0] = fma2(X, w2.x, acc[2][0]); acc[2][1] = fma2(X, w2.y, acc[2][1]);
                X = dup2(xv4.w); acc[3][0] = fma2(X, w2.x, acc[3][0]); acc[3][1] = fma2(X, w2.y, acc[3][1]);
            }
            float4 bo = *(const float4*)(Bs[m] + tx * 4);
            float* out = Os[m];
#pragma unroll
            for (int pp = 0; pp < 4; pp++) {
                float c0, c1, c2, c3;
                unpack2(acc[pp][0], c0, c1);
                unpack2(acc[pp][1], c2, c3);
                *(float4*)(out + (pbase + ty * 4 + pp) * 64 + tx * 4) =
                    make_float4(c0 + bo.x, c1 + bo.y, c2 + bo.z, c3 + bo.w);
            }
        }
    } else {
        const int sbid = bid - GEMM_BLOCKS;
        float w00 = Wp1[0], w01 = Wp1[1], w02 = Wp1[2];
        float w10 = Wp1[3], w11 = Wp1[4], w12 = Wp1[5];
        float w20 = Wp1[6], w21 = Wp1[7], w22 = Wp1[8];
        float b0 = bp1[0], b1 = bp1[1], b2 = bp1[2];

        float s0 = 0, s1 = 0, s2 = 0, q0 = 0, q1 = 0, q2 = 0;
        int bbase = sbid * 1024;
#pragma unroll
        for (int i = 0; i < 4; i++) {
            int sid = bbase + i * 256 + t;
            int n = sid >> 4;
            int j = idx[sid];
            float dx = p[j * 3 + 0] - p[n * 3 + 0];
            float dy = p[j * 3 + 1] - p[n * 3 + 1];
            float dz = p[j * 3 + 2] - p[n * 3 + 2];
            float a0 = w00 * dx + w01 * dy + w02 * dz + b0;
            float a1 = w10 * dx + w11 * dy + w12 * dz + b1;
            float a2 = w20 * dx + w21 * dy + w22 * dz + b2;
            g_jr[sid] = make_float4(a0, a1, a2, __int_as_float(j));
            s0 += a0; s1 += a1; s2 += a2;
            q0 += a0 * a0; q1 += a1 * a1; q2 += a2 * a2;
        }
#pragma unroll
        for (int o = 16; o; o >>= 1) {
            s0 += __shfl_xor_sync(0xffffffffu, s0, o);
            s1 += __shfl_xor_sync(0xffffffffu, s1, o);
            s2 += __shfl_xor_sync(0xffffffffu, s2, o);
            q0 += __shfl_xor_sync(0xffffffffu, q0, o);
            q1 += __shfl_xor_sync(0xffffffffu, q1, o);
            q2 += __shfl_xor_sync(0xffffffffu, q2, o);
        }
        int w = t >> 5, lane = t & 31;
        if (lane == 0) {
            red[w][0] = s0; red[w][1] = s1; red[w][2] = s2;
            red[w][3] = q0; red[w][4] = q1; red[w][5] = q2;
        }
        __syncthreads();
        if (t < 6) {
            float acc = 0.f;
#pragma unroll
            for (int i = 0; i < 8; i++) acc += red[i][t];
            g_pP[t][sbid] = acc;
        }
    }
}

// ---------------- K3: stats of w = xk[idx] - xq + p_r2 -----------------------
// grid 1024; block 256 (8 warps); warp handles 8 points (128 samples staged).
__global__ __launch_bounds__(256) void k_statsW1(
    const float* __restrict__ Wp2, const float* __restrict__ bp2,
    const float* __restrict__ gp, const float* __restrict__ betap) {
    __shared__ __align__(16) float4 sh_jr[8][128];
    __shared__ float sred[128];
    __shared__ float sP6[6];
    int t = threadIdx.x, w = t >> 5, l = t & 31;

    if (t < 192) {
        int ch = t >> 5, ln = t & 31;
        float s = 0.f;
#pragma unroll
        for (int i = 0; i < 32; i++) s += g_pP[ch][ln + 32 * i];
#pragma unroll
        for (int o = 16; o; o >>= 1) s += __shfl_xor_sync(0xffffffffu, s, o);
        if (ln == 0) sP6[ch] = s;
    }
    if (t < 128) sred[t] = 0.f;
    __syncthreads();
    if (blockIdx.x == 0 && t < 6) g_sPf[t] = sP6[t];

    float aP[3], bP[3];
#pragma unroll
    for (int c = 0; c < 3; c++) {
        float m = sP6[c] / CNT;
        float v = sP6[3 + c] / CNT - m * m;
        aP[c] = gp[c] * rsqrtf(v + EPS);
        bP[c] = betap[c] - m * aP[c];
    }

    const int c0 = 2 * l;
    ull WA0 = pack2(Wp2[c0 * 3],     Wp2[(c0 + 1) * 3]);
    ull WA1 = pack2(Wp2[c0 * 3 + 1], Wp2[(c0 + 1) * 3 + 1]);
    ull WA2 = pack2(Wp2[c0 * 3 + 2], Wp2[(c0 + 1) * 3 + 2]);
    float bq0 = bp2[c0], bq1 = bp2[c0 + 1];

    int pwarp = (blockIdx.x * 8 + w) * 8;
#pragma unroll
    for (int i = 0; i < 4; i++) {
        int sl = 32 * i + l;
        int sid = pwarp * 16 + sl;
        float4 a = g_jr[sid];
        float r0 = fmaxf(aP[0] * a.x + bP[0], 0.f);
        float r1 = fmaxf(aP[1] * a.y + bP[1], 0.f);
        float r2 = fmaxf(aP[2] * a.z + bP[2], 0.f);
        sh_jr[w][sl] = make_float4(r0, r1, r2, a.w);
    }
    __syncwarp();

    ull S = 0ULL, SS = 0ULL;
#pragma unroll
    for (int pp = 0; pp < 8; pp++) {
        int n = pwarp + pp;
        float2 q2 = *(const float2*)(g_xq + n * 64 + c0);
        ull base = pack2(bq0 - q2.x, bq1 - q2.y);
#pragma unroll
        for (int k = 0; k < 16; k++) {
            float4 jr = sh_jr[w][pp * 16 + k];
            int j = __float_as_int(jr.w);
            ull pr = fma2(dup2(jr.z), WA2,
                      fma2(dup2(jr.y), WA1,
                      fma2(dup2(jr.x), WA0, base)));
            ull xk2 = *(const ull*)(g_xk + j * 64 + c0);
            ull wv = add2(xk2, pr);
            S  = add2(S, wv);
            SS = fma2(wv, wv, SS);
        }
    }
    float s0, s1, q0, q1;
    unpack2(S, s0, s1);
    unpack2(SS, q0, q1);
    atomicAdd(&sred[c0], s0);
    atomicAdd(&sred[c0 + 1], s1);
    atomicAdd(&sred[64 + c0], q0);
    atomicAdd(&sred[64 + c0 + 1], q1);
    __syncthreads();
    if (t < 128) atomicAdd(&g_sW1[t], sred[t]);
}

// ---------------- BN-P constants from finalized sums -------------------------
__device__ __forceinline__ void bnp_coef_f(const float* gp, const float* betap,
                                           float* aP, float* bP) {
#pragma unroll
    for (int c = 0; c < 3; c++) {
        float m = g_sPf[c] / CNT;
        float v = g_sPf[3 + c] / CNT - m * m;
        aP[c] = gp[c] * rsqrtf(v + EPS);
        bP[c] = betap[c] - m * aP[c];
    }
}

// ---------------- K4: w8 = relu(bn1(w)) @ Ww1^T + bw1, + stats ---------------
// grid 2048; block 128 (4 warps); warp handles 8 points in 4 tiles of 2.
__global__ __launch_bounds__(128) void k_w8(
    const float* __restrict__ Wp2, const float* __restrict__ bp2,
    const float* __restrict__ gp, const float* __restrict__ betap,
    const float* __restrict__ gw1, const float* __restrict__ betaw1,
    const float* __restrict__ Ww1, const float* __restrict__ bw1) {
    __shared__ __align__(16) float sh_h[4][32 * 68];
    __shared__ __align__(16) float4 sh_jr[4][32];
    __shared__ __align__(16) float ww1s[8][64];
    __shared__ float sred2[16];
    int t = threadIdx.x, w = t >> 5, l = t & 31;
    if (t < 16) sred2[t] = 0.f;
    for (int e = t; e < 512; e += 128) ww1s[e >> 6][e & 63] = Ww1[e];

    float aP[3], bP[3];
    bnp_coef_f(gp, betap, aP, bP);

    const int c0 = 2 * l;
    ull WA0 = pack2(Wp2[c0 * 3],     Wp2[(c0 + 1) * 3]);
    ull WA1 = pack2(Wp2[c0 * 3 + 1], Wp2[(c0 + 1) * 3 + 1]);
    ull WA2 = pack2(Wp2[c0 * 3 + 2], Wp2[(c0 + 1) * 3 + 2]);
    float bq0 = bp2[c0], bq1 = bp2[c0 + 1];

    float m0 = g_sW1[c0] / CNT,     v0 = g_sW1[64 + c0] / CNT - m0 * m0;
    float A0 = gw1[c0] * rsqrtf(v0 + EPS), B0 = betaw1[c0] - m0 * A0;
    float m1 = g_sW1[c0 + 1] / CNT, v1 = g_sW1[64 + c0 + 1] / CNT - m1 * m1;
    float A1 = gw1[c0 + 1] * rsqrtf(v1 + EPS), B1 = betaw1[c0 + 1] - m1 * A1;
    ull A1p = pack2(A0, A1), B1p = pack2(B0, B1);

    float bw[8];
#pragma unroll
    for (int r = 0; r < 8; r++) bw[r] = bw1[r];
    float sw[8], sq[8];
#pragma unroll
    for (int r = 0; r < 8; r++) { sw[r] = 0.f; sq[r] = 0.f; }

    int pwarp = (blockIdx.x * 4 + w) * 8;
    __syncthreads();

    for (int tt = 0; tt < 4; tt++) {
        int pA = pwarp + tt * 2;
        {   // stage 2 points x 16 neighbors, packed (r0,r1,r2,j)
            int sid = (pA + (l >> 4)) * 16 + (l & 15);
            float4 a = g_jr[sid];
            float r0 = fmaxf(aP[0] * a.x + bP[0], 0.f);
            float r1 = fmaxf(aP[1] * a.y + bP[1], 0.f);
            float r2 = fmaxf(aP[2] * a.z + bP[2], 0.f);
            sh_jr[w][l] = make_float4(r0, r1, r2, a.w);
        }
        float2 qA = *(const float2*)(g_xq + pA * 64 + c0);
        float2 qB = *(const float2*)(g_xq + (pA + 1) * 64 + c0);
        ull base0 = pack2(bq0 - qA.x, bq1 - qA.y);
        ull base1 = pack2(bq0 - qB.x, bq1 - qB.y);
        __syncwarp();
#pragma unroll
        for (int kk = 0; kk < 32; kk++) {
            float4 jr = sh_jr[w][kk];
            int j = __float_as_int(jr.w);
            ull base = (kk < 16) ? base0 : base1;
            ull pr = fma2(dup2(jr.z), WA2,
                      fma2(dup2(jr.y), WA1,
                      fma2(dup2(jr.x), WA0, base)));
            ull xk2 = *(const ull*)(g_xk + j * 64 + c0);
            ull u = add2(xk2, pr);
            ull hp = fma2(A1p, u, B1p);
            float h0, h1;
            unpack2(hp, h0, h1);
            h0 = fmaxf(h0, 0.f); h1 = fmaxf(h1, 0.f);
            *(ull*)(sh_h[w] + kk * 68 + c0) = pack2(h0, h1);
        }
        __syncwarp();
        ull Y[8];
#pragma unroll
        for (int r = 0; r < 8; r++) Y[r] = 0ULL;
        const ulonglong2* hv = (const ulonglong2*)(sh_h[w] + l * 68);
#pragma unroll
        for (int cc = 0; cc < 16; cc++) {
            ulonglong2 h2 = hv[cc];
#pragma unroll
            for (int r = 0; r < 8; r++) {
                ulonglong2 w2 = *(const ulonglong2*)(&ww1s[r][cc * 4]);
                Y[r] = fma2(h2.x, w2.x, Y[r]);
                Y[r] = fma2(h2.y, w2.y, Y[r]);
            }
        }
        float y[8];
#pragma unroll
        for (int r = 0; r < 8; r++) {
            float a, b;
            unpack2(Y[r], a, b);
            y[r] = bw[r] + a + b;
        }
        int sid = pA * 16 + l;
        *(float4*)(g_w8 + sid * 8)     = make_float4(y[0], y[1], y[2], y[3]);
        *(float4*)(g_w8 + sid * 8 + 4) = make_float4(y[4], y[5], y[6], y[7]);
#pragma unroll
        for (int r = 0; r < 8; r++) { sw[r] += y[r]; sq[r] += y[r] * y[r]; }
        __syncwarp();
    }
#pragma unroll
    for (int o = 16; o; o >>= 1) {
#pragma unroll
        for (int r = 0; r < 8; r++) {
            sw[r] += __shfl_xor_sync(0xffffffffu, sw[r], o);
            sq[r] += __shfl_xor_sync(0xffffffffu, sq[r], o);
        }
    }
    if (l == 0) {
#pragma unroll
        for (int r = 0; r < 8; r++) {
            atomicAdd(&sred2[r], sw[r]);
            atomicAdd(&sred2[8 + r], sq[r]);
        }
    }
    __syncthreads();
    if (t < 16) atomicAdd(&g_sW2[t], sred2[t]);
}

// ---------------- K5: bn2 + relu + 8x8 matvec + softmax + aggregate ----------
// grid 4096; block 256 (8 warps); warp handles 2 points.
__global__ __launch_bounds__(256) void k_final(
    const float* __restrict__ Wp2, const float* __restrict__ bp2,
    const float* __restrict__ gp, const float* __restrict__ betap,
    const float* __restrict__ gw2, const float* __restrict__ betaw2,
    const float* __restrict__ Ww2, const float* __restrict__ bw2,
    float* __restrict__ out) {
    __shared__ __align__(16) ull sh_sT[8][32][5];  // [warp][sample][mpair+pad]
    __shared__ __align__(16) float4 sh_jr[8][32];
    int t = threadIdx.x, w = t >> 5, l = t & 31;

    float aP[3], bP[3];
    bnp_coef_f(gp, betap, aP, bP);

    float A2[8], B2[8];
#pragma unroll
    for (int r = 0; r < 8; r++) {
        float m = g_sW2[r] / CNT;
        float v = g_sW2[8 + r] / CNT - m * m;
        A2[r] = gw2[r] * rsqrtf(v + EPS);
        B2[r] = betaw2[r] - m * A2[r];
    }

    const int c0 = 2 * l;
    ull WA0 = pack2(Wp2[c0 * 3],     Wp2[(c0 + 1) * 3]);
    ull WA1 = pack2(Wp2[c0 * 3 + 1], Wp2[(c0 + 1) * 3 + 1]);
    ull WA2 = pack2(Wp2[c0 * 3 + 2], Wp2[(c0 + 1) * 3 + 2]);
    ull BBp = pack2(bp2[c0], bp2[c0 + 1]);

    int pbase = (blockIdx.x * 8 + w) * 2;
    int sid = (pbase + (l >> 4)) * 16 + (l & 15);
    {
        float4 a = g_jr[sid];
        float r0 = fmaxf(aP[0] * a.x + bP[0], 0.f);
        float r1 = fmaxf(aP[1] * a.y + bP[1], 0.f);
        float r2 = fmaxf(aP[2] * a.z + bP[2], 0.f);
        sh_jr[w][l] = make_float4(r0, r1, r2, a.w);
    }

    float4 y0 = *(const float4*)(g_w8 + sid * 8);
    float4 y1 = *(const float4*)(g_w8 + sid * 8 + 4);
    float h[8] = {y0.x, y0.y, y0.z, y0.w, y1.x, y1.y, y1.z, y1.w};
#pragma unroll
    for (int r = 0; r < 8; r++) h[r] = fmaxf(A2[r] * h[r] + B2[r], 0.f);

    float z[8];
#pragma unroll
    for (int r = 0; r < 8; r++) {
        float acc = bw2[r];
#pragma unroll
        for (int i = 0; i < 8; i++) acc += h[i] * Ww2[r * 8 + i];
        z[r] = acc;
    }
    // softmax over 16 neighbors (xor <= 8 keeps 16-lane halves independent)
#pragma unroll
    for (int r = 0; r < 8; r++) {
        float mx = z[r];
#pragma unroll
        for (int o = 8; o; o >>= 1) mx = fmaxf(mx, __shfl_xor_sync(0xffffffffu, mx, o));
        float e = __expf(z[r] - mx);
        float sm = e;
#pragma unroll
        for (int o = 8; o; o >>= 1) sm += __shfl_xor_sync(0xffffffffu, sm, o);
        z[r] = e / sm;
    }
    // conflict-free padded store: lane-major rows, pair index within row
#pragma unroll
    for (int p2 = 0; p2 < 4; p2++)
        sh_sT[w][l][p2] = pack2(z[2 * p2], z[2 * p2 + 1]);
    __syncwarp();

    // aggregate: lane l owns channels (2l, 2l+1)
    const int mp = l & 3;
#pragma unroll
    for (int pp = 0; pp < 2; pp++) {
        int n = pbase + pp;
        ull ACC = 0ULL;
#pragma unroll
        for (int k = 0; k < 16; k++) {
            int kk = pp * 16 + k;
            float4 jr = sh_jr[w][kk];
            int jg = __float_as_int(jr.w);
            ull pr = fma2(dup2(jr.z), WA2,
                      fma2(dup2(jr.y), WA1,
                      fma2(dup2(jr.x), WA0, BBp)));
            ull xv2 = *(const ull*)(g_xv + jg * 64 + c0);
            ull tv = add2(xv2, pr);
            ull s2 = sh_sT[w][kk][mp];
            ACC = fma2(tv, s2, ACC);
        }
        float a0, a1;
        unpack2(ACC, a0, a1);
        *(float2*)(out + n * 64 + c0) = make_float2(a0, a1);
    }
}

// ---------------- launch ------------------------------------------------------
extern "C" void kernel_launch(void* const* d_in, const int* in_sizes, int n_in,
                              void* d_out, int out_size) {
    const float* p     = (const float*)d_in[0];
    const float* x     = (const float*)d_in[1];
    const int*   idx   = (const int*)d_in[2];
    const float* Wq    = (const float*)d_in[3];
    const float* bq    = (const float*)d_in[4];
    const float* Wk    = (const float*)d_in[5];
    const float* bk    = (const float*)d_in[6];
    const float* Wv    = (const float*)d_in[7];
    const float* bv    = (const float*)d_in[8];
    const float* Wp1   = (const float*)d_in[9];
    const float* bp1   = (const float*)d_in[10];
    const float* gp    = (const float*)d_in[11];
    const float* betap = (const float*)d_in[12];
    const float* Wp2   = (const float*)d_in[13];
    const float* bp2   = (const float*)d_in[14];
    const float* gw1   = (const float*)d_in[15];
    const float* betaw1= (const float*)d_in[16];
    const float* Ww1   = (const float*)d_in[17];
    const float* bw1   = (const float*)d_in[18];
    const float* gw2   = (const float*)d_in[19];
    const float* betaw2= (const float*)d_in[20];
    const float* Ww2   = (const float*)d_in[21];
    const float* bw2   = (const float*)d_in[22];
    float* out = (float*)d_out;

    k_gemm_statsP<<<2048, 256>>>(x, p, idx, Wq, bq, Wk, bk, Wv, bv, Wp1, bp1);
    k_statsW1<<<1024, 256>>>(Wp2, bp2, gp, betap);
    k_w8<<<2048, 128>>>(Wp2, bp2, gp, betap, gw1, betaw1, Ww1, bw1);
    k_final<<<4096, 256>>>(Wp2, bp2, gp, betap, gw2, betaw2, Ww2, bw2, out);
}